// round 10
// baseline (speedup 1.0000x reference)
#include <cuda_runtime.h>
#include <math.h>

// Problem shape (fixed by setup_inputs): X (32, 64, 25, 2, 16, 16) fp32.
#define S_N     32
#define TVM     3200
#define NE      256
#define CHUNKS  32
#define CHUNK_M 100

// ---------------- device scratch (no allocations allowed) ----------------
__device__ float g_partial[S_N * CHUNKS * NE];
__device__ float g_xmean[S_N * NE];
__device__ float g_L[S_N * NE];
__device__ float g_Gs[NE], g_Gi[NE];
__device__ float g_As[NE], g_Ai[NE];
__device__ float g_C[NE];

// =========================================================================
// K1: partial reduction of X. grid (32,32), 256 thr; 100 matrices / block.
// =========================================================================
__global__ __launch_bounds__(256) void k_partial(const float* __restrict__ X) {
    __shared__ float4 red[256];
    int s = blockIdx.x, c = blockIdx.y, t = threadIdx.x;
    int j = t & 63, gsub = t >> 6;
    const float4* p = (const float4*)(X + ((size_t)s * TVM + (size_t)c * CHUNK_M) * NE)
                      + (size_t)gsub * 25 * 64 + j;
    float4 a = make_float4(0.f, 0.f, 0.f, 0.f);
#pragma unroll
    for (int m = 0; m < 25; ++m) {
        float4 v = p[(size_t)m * 64];
        a.x += v.x; a.y += v.y; a.z += v.z; a.w += v.w;
    }
    red[t] = a;
    __syncthreads();
    if (t < 64) {
        float4 b0 = red[t], b1 = red[t + 64], b2 = red[t + 128], b3 = red[t + 192];
        float4 r = make_float4((b0.x + b1.x) + (b2.x + b3.x),
                               (b0.y + b1.y) + (b2.y + b3.y),
                               (b0.z + b1.z) + (b2.z + b3.z),
                               (b0.w + b1.w) + (b2.w + b3.w));
        ((float4*)(g_partial + (s * CHUNKS + c) * NE))[t] = r;
    }
}

// =========================================================================
// K2: per-sample means. grid 32, 256 thr.
// =========================================================================
__global__ __launch_bounds__(256) void k_samplemean() {
    int b = blockIdx.x, t = threadIdx.x;
    float acc = 0.f;
#pragma unroll 8
    for (int c = 0; c < CHUNKS; ++c) acc += g_partial[(b * CHUNKS + c) * NE + t];
    g_xmean[b * NE + t] = acc * (1.f / (float)TVM);
}

// =========================================================================
// Warp-level 16x16 toolkit (matrix = 256 contiguous floats, row-major).
// Iteration counts derived ONCE from the initial error norm.
// =========================================================================
__device__ __forceinline__ float wsum32(float v) {
#pragma unroll
    for (int o = 16; o; o >>= 1) v += __shfl_xor_sync(0xffffffffu, v, o);
    return v;
}
__device__ __forceinline__ float wmax32(float v) {
#pragma unroll
    for (int o = 16; o; o >>= 1) v = fmaxf(v, __shfl_xor_sync(0xffffffffu, v, o));
    return v;
}
__device__ __forceinline__ float w_trace16(const float* A, int lane) {
    float v = (lane < 16) ? A[lane * 17] : 0.f;
    return wsum32(v);
}

__device__ __forceinline__ void wmm16(float* C, const float* A, const float* B, int lane) {
    int i = lane >> 1, jb = (lane & 1) << 3;
    const float4* ar = (const float4*)(A + i * 16);
    float4 v0 = ar[0], v1 = ar[1], v2 = ar[2], v3 = ar[3];
    float a[16] = {v0.x, v0.y, v0.z, v0.w, v1.x, v1.y, v1.z, v1.w,
                   v2.x, v2.y, v2.z, v2.w, v3.x, v3.y, v3.z, v3.w};
    float c[8] = {0.f, 0.f, 0.f, 0.f, 0.f, 0.f, 0.f, 0.f};
#pragma unroll
    for (int k = 0; k < 16; ++k) {
        const float4* br = (const float4*)(B + k * 16 + jb);
        float4 b0 = br[0], b1 = br[1];
        float ak = a[k];
        c[0] = fmaf(ak, b0.x, c[0]); c[1] = fmaf(ak, b0.y, c[1]);
        c[2] = fmaf(ak, b0.z, c[2]); c[3] = fmaf(ak, b0.w, c[3]);
        c[4] = fmaf(ak, b1.x, c[4]); c[5] = fmaf(ak, b1.y, c[5]);
        c[6] = fmaf(ak, b1.z, c[6]); c[7] = fmaf(ak, b1.w, c[7]);
    }
    __syncwarp();
    float4* cr = (float4*)(C + i * 16 + jb);
    cr[0] = make_float4(c[0], c[1], c[2], c[3]);
    cr[1] = make_float4(c[4], c[5], c[6], c[7]);
    __syncwarp();
}

__device__ void w_sqrtinv(const float* A, float* Y, float* Z,
                          float* T, float* Y2, float* Z2, int lane) {
    float s = w_trace16(A, lane) * (1.f / 16.f);
    float is0 = 1.f / s, d2 = 0.f;
#pragma unroll
    for (int q = 0; q < 8; ++q) {
        int idx = q * 32 + lane; int r = idx >> 4, c = idx & 15;
        float v = A[idx] * is0 - (r == c ? 1.f : 0.f);
        d2 += v * v;
    }
    d2 = wsum32(d2);
    int n;
    if (d2 >= 0.81f) {
        float rs = 0.f;
        if (lane < 16) { for (int k = 0; k < 16; ++k) rs += fabsf(A[lane * 16 + k]); }
        rs = wmax32(rs);
        s = rs; is0 = 1.f / s; n = 12;
    } else {
        float cur = sqrtf(d2); n = 0;
        while (cur > 1e-7f && n < 7) { cur = 1.3f * cur * cur; ++n; }
    }
#pragma unroll
    for (int q = 0; q < 8; ++q) {
        int idx = q * 32 + lane; int r = idx >> 4, c = idx & 15;
        Y[idx] = A[idx] * is0;
        Z[idx] = (r == c) ? 1.f : 0.f;
    }
    __syncwarp();
    float* y = Y; float* z = Z; float* y2 = Y2; float* z2 = Z2;
    for (int it = 0; it < n; ++it) {
        wmm16(T, z, y, lane);
#pragma unroll
        for (int q = 0; q < 8; ++q) {
            int idx = q * 32 + lane; int r = idx >> 4, c = idx & 15;
            T[idx] = 0.5f * ((r == c ? 3.f : 0.f) - T[idx]);
        }
        __syncwarp();
        wmm16(y2, y, T, lane);
        wmm16(z2, T, z, lane);
        float* tm = y; y = y2; y2 = tm;
        tm = z; z = z2; z2 = tm;
    }
    float fs = sqrtf(s), fi = rsqrtf(s);
    float ry[8], rz[8];
#pragma unroll
    for (int q = 0; q < 8; ++q) { int idx = q * 32 + lane; ry[q] = y[idx] * fs; rz[q] = z[idx] * fi; }
    __syncwarp();
#pragma unroll
    for (int q = 0; q < 8; ++q) { int idx = q * 32 + lane; Y[idx] = ry[q]; Z[idx] = rz[q]; }
    __syncwarp();
}

__device__ void w_logm(float* B, float* t1, float* t2, float* t3,
                       float* t4, float* t5, int lane) {
    int jsq = 0; float s, d2;
    for (;;) {
        s = w_trace16(B, lane) * (1.f / 16.f);
        float is = 1.f / s; d2 = 0.f;
#pragma unroll
        for (int q = 0; q < 8; ++q) {
            int idx = q * 32 + lane; int r = idx >> 4, c = idx & 15;
            float v = B[idx] * is - (r == c ? 1.f : 0.f);
            t1[idx] = v; d2 += v * v;
        }
        __syncwarp();
        d2 = wsum32(d2);
        if (d2 <= 0.25f || jsq >= 4) break;
        w_sqrtinv(B, t2, t3, t4, t5, t1, lane);
        float r8[8];
#pragma unroll
        for (int q = 0; q < 8; ++q) r8[q] = t2[q * 32 + lane];
        __syncwarp();
#pragma unroll
        for (int q = 0; q < 8; ++q) B[q * 32 + lane] = r8[q];
        __syncwarp();
        ++jsq;
    }
    float d = sqrtf(d2);
    int nt = 1; { float r = d; while (r > 1e-7f && nt < 24) { r *= d; ++nt; } }
    float lns = logf(s);
#pragma unroll
    for (int q = 0; q < 8; ++q) {
        int idx = q * 32 + lane; int r = idx >> 4, c = idx & 15;
        float v = t1[idx];
        B[idx] = (r == c ? lns : 0.f) + v;
        t2[idx] = v;
    }
    __syncwarp();
    float* P = t2; float* P2 = t3; float sg = 1.f;
    for (int k = 2; k <= nt; ++k) {
        wmm16(P2, P, t1, lane);
        sg = -sg; float cf = sg / (float)k;
#pragma unroll
        for (int q = 0; q < 8; ++q) { int idx = q * 32 + lane; B[idx] += cf * P2[idx]; }
        __syncwarp();
        float* tm = P; P = P2; P2 = tm;
    }
    if (jsq) {
        float f = (float)(1 << jsq);
#pragma unroll
        for (int q = 0; q < 8; ++q) B[q * 32 + lane] *= f;
        __syncwarp();
    }
}

__device__ void w_expm(const float* A, float* R, float* t1, float* t2, float* t3, int lane) {
    float c0 = w_trace16(A, lane) * (1.f / 16.f);
    float d2 = 0.f;
#pragma unroll
    for (int q = 0; q < 8; ++q) {
        int idx = q * 32 + lane; int r = idx >> 4, c = idx & 15;
        float v = A[idx] - (r == c ? c0 : 0.f);
        t1[idx] = v; d2 += v * v;
    }
    __syncwarp();
    d2 = wsum32(d2);
    int j = 0; float sc = 1.f;
    while (d2 > 0.25f && j < 20) { sc *= 0.5f; d2 *= 0.25f; ++j; }
    if (j) {
#pragma unroll
        for (int q = 0; q < 8; ++q) t1[q * 32 + lane] *= sc;
        __syncwarp();
    }
    float d = sqrtf(d2);
    int nt = 1; { float r = d; while (r > 1e-7f && nt < 14) { ++nt; r *= d / (float)nt; } }
    float ec = expf(c0 * sc);
#pragma unroll
    for (int q = 0; q < 8; ++q) {
        int idx = q * 32 + lane; int r = idx >> 4, c = idx & 15;
        float v = t1[idx];
        R[idx] = (r == c ? 1.f : 0.f) + v;
        t2[idx] = v;
    }
    __syncwarp();
    float* P = t2; float* P2 = t3;
    for (int k = 2; k <= nt; ++k) {
        wmm16(P2, P, t1, lane);
        float ik = 1.f / (float)k;
#pragma unroll
        for (int q = 0; q < 8; ++q) { int idx = q * 32 + lane; float v = P2[idx] * ik; P2[idx] = v; R[idx] += v; }
        __syncwarp();
        float* tm = P; P = P2; P2 = tm;
    }
#pragma unroll
    for (int q = 0; q < 8; ++q) R[q * 32 + lane] *= ec;
    __syncwarp();
    for (int q2 = 0; q2 < j; ++q2) {
        wmm16(t2, R, R, lane);
#pragma unroll
        for (int q = 0; q < 8; ++q) R[q * 32 + lane] = t2[q * 32 + lane];
        __syncwarp();
    }
}

// =========================================================================
// K3: warp0: (Gs,Gi) of G = mean_b xmean_b || warp1: (As,Ai) of rm
// =========================================================================
__global__ __launch_bounds__(64) void k_prep(const float* __restrict__ rm) {
    __shared__ __align__(16) float ws[2][6][256];
    int t = threadIdx.x, w = t >> 5, lane = t & 31;
    float* b0 = ws[w][0]; float* b1 = ws[w][1]; float* b2 = ws[w][2];
    float* b3 = ws[w][3]; float* b4 = ws[w][4]; float* b5 = ws[w][5];
    if (w == 0) {
#pragma unroll
        for (int q = 0; q < 8; ++q) {
            int idx = q * 32 + lane;
            float acc = 0.f;
#pragma unroll 8
            for (int b = 0; b < S_N; ++b) acc += g_xmean[b * NE + idx];
            b0[idx] = acc * (1.f / (float)S_N);
        }
        __syncwarp();
        w_sqrtinv(b0, b1, b2, b3, b4, b5, lane);
#pragma unroll
        for (int q = 0; q < 8; ++q) { int idx = q * 32 + lane; g_Gs[idx] = b1[idx]; g_Gi[idx] = b2[idx]; }
    } else {
#pragma unroll
        for (int q = 0; q < 8; ++q) { int idx = q * 32 + lane; b0[idx] = rm[idx]; }
        __syncwarp();
        w_sqrtinv(b0, b1, b2, b3, b4, b5, lane);
#pragma unroll
        for (int q = 0; q < 8; ++q) { int idx = q * 32 + lane; g_As[idx] = b1[idx]; g_Ai[idx] = b2[idx]; }
    }
}

// =========================================================================
// K4: L_b = logm(Gi * xmean_b * Gi); 32 one-warp blocks in parallel.
// =========================================================================
__global__ __launch_bounds__(32) void k_logm() {
    __shared__ __align__(16) float m[6][256];
    int b = blockIdx.x, lane = threadIdx.x;
#pragma unroll
    for (int q = 0; q < 8; ++q) {
        int idx = q * 32 + lane;
        m[0][idx] = g_Gi[idx];
        m[1][idx] = g_xmean[b * NE + idx];
    }
    __syncwarp();
    wmm16(m[2], m[0], m[1], lane);
    wmm16(m[3], m[2], m[0], lane);
    w_logm(m[3], m[0], m[1], m[2], m[4], m[5], lane);
#pragma unroll
    for (int q = 0; q < 8; ++q) { int idx = q * 32 + lane; g_L[b * NE + idx] = m[3][idx]; }
}

// =========================================================================
// K5: mean = Gs expm(mean L) Gs; warp0: C = invsqrt(mean) -> g_C
//     || warp1: geodesic(rm, mean, 0.1) -> out tail.
// =========================================================================
__global__ __launch_bounds__(64) void k_finish(float* __restrict__ out_tail, int write_tail) {
    __shared__ __align__(16) float ws[2][6][256];
    __shared__ __align__(16) float sMean[256];
    int t = threadIdx.x, w = t >> 5, lane = t & 31;
    float* b0 = ws[w][0]; float* b1 = ws[w][1]; float* b2 = ws[w][2];
    float* b3 = ws[w][3]; float* b4 = ws[w][4]; float* b5 = ws[w][5];
    if (w == 0) {
#pragma unroll
        for (int q = 0; q < 8; ++q) {
            int idx = q * 32 + lane;
            float acc = 0.f;
#pragma unroll 8
            for (int b = 0; b < S_N; ++b) acc += g_L[b * NE + idx];
            b0[idx] = acc * (1.f / (float)S_N);
        }
        __syncwarp();
        w_expm(b0, b1, b2, b3, b4, lane);
        {
#pragma unroll
            for (int q = 0; q < 8; ++q) { int idx = q * 32 + lane; b2[idx] = g_Gs[idx]; }
            __syncwarp();
        }
        wmm16(b3, b2, b1, lane);
        wmm16(sMean, b3, b2, lane);
    }
    __syncthreads();
    if (w == 0) {
        w_sqrtinv(sMean, b0, b1, b2, b3, b4, lane);
#pragma unroll
        for (int q = 0; q < 8; ++q) { int idx = q * 32 + lane; g_C[idx] = b1[idx]; }
    } else {
#pragma unroll
        for (int q = 0; q < 8; ++q) { int idx = q * 32 + lane; b0[idx] = g_Ai[idx]; }
        __syncwarp();
        wmm16(b1, b0, sMean, lane);
        wmm16(b2, b1, b0, lane);
        w_logm(b2, b0, b1, b3, b4, b5, lane);
#pragma unroll
        for (int q = 0; q < 8; ++q) b2[q * 32 + lane] *= 0.1f;
        __syncwarp();
        w_expm(b2, b0, b1, b3, b4, lane);
#pragma unroll
        for (int q = 0; q < 8; ++q) { int idx = q * 32 + lane; b1[idx] = g_As[idx]; }
        __syncwarp();
        wmm16(b3, b1, b0, lane);
        wmm16(b4, b3, b1, lane);
        if (write_tail) {
#pragma unroll
            for (int q = 0; q < 8; ++q) { int idx = q * 32 + lane; out_tail[idx] = b4[idx]; }
        }
    }
}

// =========================================================================
// K6 (transform v5): Y = C*X*C, C symmetric. 2 rows/thread (same matrix),
// 8 thr/matrix, 32 matrices/block. No inter-phase sync needed:
//   z_r = C_row_r * X   (X rows from staged smem, shared by both rows)
//   y_r = z_r * C       (C rows uniform broadcast)
// C scalars via one LDS.64/k using symmetry: C[r][k],C[r+1][k] = Cs[k*16+r..r+1].
// No register arrays for C -> no spills. launch_bounds(256,3).
// =========================================================================
typedef unsigned long long u64;
__device__ __forceinline__ u64 pk2(float lo, float hi) {
    u64 r; asm("mov.b64 %0, {%1, %2};" : "=l"(r) : "f"(lo), "f"(hi)); return r;
}
__device__ __forceinline__ void upk2(u64 v, float& lo, float& hi) {
    asm("mov.b64 {%0, %1}, %2;" : "=f"(lo), "=f"(hi) : "l"(v));
}
__device__ __forceinline__ u64 ffma2(u64 a, u64 b, u64 c) {
    u64 d; asm("fma.rn.f32x2 %0, %1, %2, %3;" : "=l"(d) : "l"(a), "l"(b), "l"(c)); return d;
}

#define TMPB  32    // matrices per block (256 threads, 8 per matrix)
#define XS4   66    // per-matrix float4 stride in Xs (1056 B: banks skew 8)

__global__ __launch_bounds__(256, 3) void k_transform(const float* __restrict__ X,
                                                      float* __restrict__ Y) {
    __shared__ float4 Xs[TMPB * XS4];   // 33 KB
    __shared__ float  Cs[256];
    int t = threadIdx.x;
    Cs[t] = g_C[t];

    const float4* xg = (const float4*)(X + (size_t)blockIdx.x * (TMPB * NE));
#pragma unroll
    for (int j = 0; j < 8; ++j) {
        int g = t + 256 * j;
        Xs[(g >> 6) * XS4 + (g & 63)] = xg[g];
    }
    __syncthreads();

    int m = t >> 3, p = t & 7;
    int r0 = 2 * p;                       // rows r0, r0+1
    const float4* xm = Xs + m * XS4;

    // phase 1: z rows r0, r0+1 of Z = C * X
    u64 z0[8], z1[8];
#pragma unroll
    for (int q = 0; q < 8; ++q) { z0[q] = pk2(0.f, 0.f); z1[q] = pk2(0.f, 0.f); }
#pragma unroll
    for (int k = 0; k < 16; ++k) {
        float4 a = xm[k * 4], b = xm[k * 4 + 1], c = xm[k * 4 + 2], d = xm[k * 4 + 3];
        float2 cs = *(const float2*)(Cs + k * 16 + r0);   // C[r0][k], C[r0+1][k] by symmetry
        u64 s0 = pk2(cs.x, cs.x);
        u64 s1 = pk2(cs.y, cs.y);
        u64 xr0 = pk2(a.x, a.y), xr1 = pk2(a.z, a.w);
        u64 xr2 = pk2(b.x, b.y), xr3 = pk2(b.z, b.w);
        u64 xr4 = pk2(c.x, c.y), xr5 = pk2(c.z, c.w);
        u64 xr6 = pk2(d.x, d.y), xr7 = pk2(d.z, d.w);
        z0[0] = ffma2(s0, xr0, z0[0]); z1[0] = ffma2(s1, xr0, z1[0]);
        z0[1] = ffma2(s0, xr1, z0[1]); z1[1] = ffma2(s1, xr1, z1[1]);
        z0[2] = ffma2(s0, xr2, z0[2]); z1[2] = ffma2(s1, xr2, z1[2]);
        z0[3] = ffma2(s0, xr3, z0[3]); z1[3] = ffma2(s1, xr3, z1[3]);
        z0[4] = ffma2(s0, xr4, z0[4]); z1[4] = ffma2(s1, xr4, z1[4]);
        z0[5] = ffma2(s0, xr5, z0[5]); z1[5] = ffma2(s1, xr5, z1[5]);
        z0[6] = ffma2(s0, xr6, z0[6]); z1[6] = ffma2(s1, xr6, z1[6]);
        z0[7] = ffma2(s0, xr7, z0[7]); z1[7] = ffma2(s1, xr7, z1[7]);
    }
    float zf0[16], zf1[16];
#pragma unroll
    for (int q = 0; q < 8; ++q) {
        upk2(z0[q], zf0[2 * q], zf0[2 * q + 1]);
        upk2(z1[q], zf1[2 * q], zf1[2 * q + 1]);
    }

    // phase 2: y rows = z rows * C (C rows uniform broadcast)
    u64 y0[8], y1[8];
#pragma unroll
    for (int q = 0; q < 8; ++q) { y0[q] = pk2(0.f, 0.f); y1[q] = pk2(0.f, 0.f); }
#pragma unroll
    for (int k = 0; k < 16; ++k) {
        const float4* cr4 = (const float4*)(Cs + k * 16);
        float4 a = cr4[0], b = cr4[1], c = cr4[2], d = cr4[3];
        u64 s0 = pk2(zf0[k], zf0[k]);
        u64 s1 = pk2(zf1[k], zf1[k]);
        u64 c0 = pk2(a.x, a.y), c1 = pk2(a.z, a.w);
        u64 c2 = pk2(b.x, b.y), c3 = pk2(b.z, b.w);
        u64 c4 = pk2(c.x, c.y), c5 = pk2(c.z, c.w);
        u64 c6 = pk2(d.x, d.y), c7 = pk2(d.z, d.w);
        y0[0] = ffma2(s0, c0, y0[0]); y1[0] = ffma2(s1, c0, y1[0]);
        y0[1] = ffma2(s0, c1, y0[1]); y1[1] = ffma2(s1, c1, y1[1]);
        y0[2] = ffma2(s0, c2, y0[2]); y1[2] = ffma2(s1, c2, y1[2]);
        y0[3] = ffma2(s0, c3, y0[3]); y1[3] = ffma2(s1, c3, y1[3]);
        y0[4] = ffma2(s0, c4, y0[4]); y1[4] = ffma2(s1, c4, y1[4]);
        y0[5] = ffma2(s0, c5, y0[5]); y1[5] = ffma2(s1, c5, y1[5]);
        y0[6] = ffma2(s0, c6, y0[6]); y1[6] = ffma2(s1, c6, y1[6]);
        y0[7] = ffma2(s0, c7, y0[7]); y1[7] = ffma2(s1, c7, y1[7]);
    }

    float4* yg = (float4*)(Y + (size_t)blockIdx.x * (TMPB * NE) + (size_t)m * NE);
#pragma unroll
    for (int q = 0; q < 4; ++q) {
        float4 v0, v1;
        upk2(y0[2 * q], v0.x, v0.y); upk2(y0[2 * q + 1], v0.z, v0.w);
        upk2(y1[2 * q], v1.x, v1.y); upk2(y1[2 * q + 1], v1.z, v1.w);
        yg[r0 * 4 + q] = v0;
        yg[(r0 + 1) * 4 + q] = v1;
    }
}

// =========================================================================
extern "C" void kernel_launch(void* const* d_in, const int* in_sizes, int n_in,
                              void* d_out, int out_size) {
    const float* X = (const float*)d_in[0];
    const float* rm = (const float*)d_in[1];
    float* out = (float*)d_out;
    long long n_x = in_sizes[0];           // 26,214,400
    int nmat = (int)(n_x >> 8);            // 102,400
    int write_tail = ((long long)out_size - n_x) >= NE ? 1 : 0;

    k_partial<<<dim3(S_N, CHUNKS), 256>>>(X);
    k_samplemean<<<S_N, 256>>>();
    k_prep<<<1, 64>>>(rm);
    k_logm<<<S_N, 32>>>();
    k_finish<<<1, 64>>>(out + n_x, write_tail);
    k_transform<<<nmat / TMPB, 256>>>(X, out);
}

// round 11
// speedup vs baseline: 1.0250x; 1.0250x over previous
#include <cuda_runtime.h>
#include <math.h>

// Problem shape (fixed by setup_inputs): X (32, 64, 25, 2, 16, 16) fp32.
#define S_N     32
#define TVM     3200
#define NE      256
#define CHUNKS  32
#define CHUNK_M 100

// ---------------- device scratch (no allocations allowed) ----------------
__device__ float g_partial[S_N * CHUNKS * NE];
__device__ float g_xmean[S_N * NE];
__device__ float g_L[S_N * NE];
__device__ float g_Gs[NE], g_Gi[NE];
__device__ float g_As[NE], g_Ai[NE];
__device__ float g_C[NE];

// =========================================================================
// K1: partial reduction of X. grid (32,32), 256 thr; 100 matrices / block.
// =========================================================================
__global__ __launch_bounds__(256) void k_partial(const float* __restrict__ X) {
    __shared__ float4 red[256];
    int s = blockIdx.x, c = blockIdx.y, t = threadIdx.x;
    int j = t & 63, gsub = t >> 6;
    const float4* p = (const float4*)(X + ((size_t)s * TVM + (size_t)c * CHUNK_M) * NE)
                      + (size_t)gsub * 25 * 64 + j;
    float4 a = make_float4(0.f, 0.f, 0.f, 0.f);
#pragma unroll
    for (int m = 0; m < 25; ++m) {
        float4 v = p[(size_t)m * 64];
        a.x += v.x; a.y += v.y; a.z += v.z; a.w += v.w;
    }
    red[t] = a;
    __syncthreads();
    if (t < 64) {
        float4 b0 = red[t], b1 = red[t + 64], b2 = red[t + 128], b3 = red[t + 192];
        float4 r = make_float4((b0.x + b1.x) + (b2.x + b3.x),
                               (b0.y + b1.y) + (b2.y + b3.y),
                               (b0.z + b1.z) + (b2.z + b3.z),
                               (b0.w + b1.w) + (b2.w + b3.w));
        ((float4*)(g_partial + (s * CHUNKS + c) * NE))[t] = r;
    }
}

// =========================================================================
// Warp-level 16x16 toolkit (matrix = 256 contiguous floats, row-major).
// Iteration counts derived ONCE from the initial error norm.
// =========================================================================
__device__ __forceinline__ float wsum32(float v) {
#pragma unroll
    for (int o = 16; o; o >>= 1) v += __shfl_xor_sync(0xffffffffu, v, o);
    return v;
}
__device__ __forceinline__ float wmax32(float v) {
#pragma unroll
    for (int o = 16; o; o >>= 1) v = fmaxf(v, __shfl_xor_sync(0xffffffffu, v, o));
    return v;
}
__device__ __forceinline__ float w_trace16(const float* A, int lane) {
    float v = (lane < 16) ? A[lane * 17] : 0.f;
    return wsum32(v);
}

__device__ __forceinline__ void wmm16(float* C, const float* A, const float* B, int lane) {
    int i = lane >> 1, jb = (lane & 1) << 3;
    const float4* ar = (const float4*)(A + i * 16);
    float4 v0 = ar[0], v1 = ar[1], v2 = ar[2], v3 = ar[3];
    float a[16] = {v0.x, v0.y, v0.z, v0.w, v1.x, v1.y, v1.z, v1.w,
                   v2.x, v2.y, v2.z, v2.w, v3.x, v3.y, v3.z, v3.w};
    float c[8] = {0.f, 0.f, 0.f, 0.f, 0.f, 0.f, 0.f, 0.f};
#pragma unroll
    for (int k = 0; k < 16; ++k) {
        const float4* br = (const float4*)(B + k * 16 + jb);
        float4 b0 = br[0], b1 = br[1];
        float ak = a[k];
        c[0] = fmaf(ak, b0.x, c[0]); c[1] = fmaf(ak, b0.y, c[1]);
        c[2] = fmaf(ak, b0.z, c[2]); c[3] = fmaf(ak, b0.w, c[3]);
        c[4] = fmaf(ak, b1.x, c[4]); c[5] = fmaf(ak, b1.y, c[5]);
        c[6] = fmaf(ak, b1.z, c[6]); c[7] = fmaf(ak, b1.w, c[7]);
    }
    __syncwarp();
    float4* cr = (float4*)(C + i * 16 + jb);
    cr[0] = make_float4(c[0], c[1], c[2], c[3]);
    cr[1] = make_float4(c[4], c[5], c[6], c[7]);
    __syncwarp();
}

__device__ void w_sqrtinv(const float* A, float* Y, float* Z,
                          float* T, float* Y2, float* Z2, int lane) {
    float s = w_trace16(A, lane) * (1.f / 16.f);
    float is0 = 1.f / s, d2 = 0.f;
#pragma unroll
    for (int q = 0; q < 8; ++q) {
        int idx = q * 32 + lane; int r = idx >> 4, c = idx & 15;
        float v = A[idx] * is0 - (r == c ? 1.f : 0.f);
        d2 += v * v;
    }
    d2 = wsum32(d2);
    int n;
    if (d2 >= 0.81f) {
        float rs = 0.f;
        if (lane < 16) { for (int k = 0; k < 16; ++k) rs += fabsf(A[lane * 16 + k]); }
        rs = wmax32(rs);
        s = rs; is0 = 1.f / s; n = 12;
    } else {
        float cur = sqrtf(d2); n = 0;
        while (cur > 1e-7f && n < 7) { cur = 1.3f * cur * cur; ++n; }
    }
#pragma unroll
    for (int q = 0; q < 8; ++q) {
        int idx = q * 32 + lane; int r = idx >> 4, c = idx & 15;
        Y[idx] = A[idx] * is0;
        Z[idx] = (r == c) ? 1.f : 0.f;
    }
    __syncwarp();
    float* y = Y; float* z = Z; float* y2 = Y2; float* z2 = Z2;
    for (int it = 0; it < n; ++it) {
        wmm16(T, z, y, lane);
#pragma unroll
        for (int q = 0; q < 8; ++q) {
            int idx = q * 32 + lane; int r = idx >> 4, c = idx & 15;
            T[idx] = 0.5f * ((r == c ? 3.f : 0.f) - T[idx]);
        }
        __syncwarp();
        wmm16(y2, y, T, lane);
        wmm16(z2, T, z, lane);
        float* tm = y; y = y2; y2 = tm;
        tm = z; z = z2; z2 = tm;
    }
    float fs = sqrtf(s), fi = rsqrtf(s);
    float ry[8], rz[8];
#pragma unroll
    for (int q = 0; q < 8; ++q) { int idx = q * 32 + lane; ry[q] = y[idx] * fs; rz[q] = z[idx] * fi; }
    __syncwarp();
#pragma unroll
    for (int q = 0; q < 8; ++q) { int idx = q * 32 + lane; Y[idx] = ry[q]; Z[idx] = rz[q]; }
    __syncwarp();
}

__device__ void w_logm(float* B, float* t1, float* t2, float* t3,
                       float* t4, float* t5, int lane) {
    int jsq = 0; float s, d2;
    for (;;) {
        s = w_trace16(B, lane) * (1.f / 16.f);
        float is = 1.f / s; d2 = 0.f;
#pragma unroll
        for (int q = 0; q < 8; ++q) {
            int idx = q * 32 + lane; int r = idx >> 4, c = idx & 15;
            float v = B[idx] * is - (r == c ? 1.f : 0.f);
            t1[idx] = v; d2 += v * v;
        }
        __syncwarp();
        d2 = wsum32(d2);
        if (d2 <= 0.25f || jsq >= 4) break;
        w_sqrtinv(B, t2, t3, t4, t5, t1, lane);
        float r8[8];
#pragma unroll
        for (int q = 0; q < 8; ++q) r8[q] = t2[q * 32 + lane];
        __syncwarp();
#pragma unroll
        for (int q = 0; q < 8; ++q) B[q * 32 + lane] = r8[q];
        __syncwarp();
        ++jsq;
    }
    float d = sqrtf(d2);
    int nt = 1; { float r = d; while (r > 1e-7f && nt < 24) { r *= d; ++nt; } }
    float lns = logf(s);
#pragma unroll
    for (int q = 0; q < 8; ++q) {
        int idx = q * 32 + lane; int r = idx >> 4, c = idx & 15;
        float v = t1[idx];
        B[idx] = (r == c ? lns : 0.f) + v;
        t2[idx] = v;
    }
    __syncwarp();
    float* P = t2; float* P2 = t3; float sg = 1.f;
    for (int k = 2; k <= nt; ++k) {
        wmm16(P2, P, t1, lane);
        sg = -sg; float cf = sg / (float)k;
#pragma unroll
        for (int q = 0; q < 8; ++q) { int idx = q * 32 + lane; B[idx] += cf * P2[idx]; }
        __syncwarp();
        float* tm = P; P = P2; P2 = tm;
    }
    if (jsq) {
        float f = (float)(1 << jsq);
#pragma unroll
        for (int q = 0; q < 8; ++q) B[q * 32 + lane] *= f;
        __syncwarp();
    }
}

__device__ void w_expm(const float* A, float* R, float* t1, float* t2, float* t3, int lane) {
    float c0 = w_trace16(A, lane) * (1.f / 16.f);
    float d2 = 0.f;
#pragma unroll
    for (int q = 0; q < 8; ++q) {
        int idx = q * 32 + lane; int r = idx >> 4, c = idx & 15;
        float v = A[idx] - (r == c ? c0 : 0.f);
        t1[idx] = v; d2 += v * v;
    }
    __syncwarp();
    d2 = wsum32(d2);
    int j = 0; float sc = 1.f;
    while (d2 > 0.25f && j < 20) { sc *= 0.5f; d2 *= 0.25f; ++j; }
    if (j) {
#pragma unroll
        for (int q = 0; q < 8; ++q) t1[q * 32 + lane] *= sc;
        __syncwarp();
    }
    float d = sqrtf(d2);
    int nt = 1; { float r = d; while (r > 1e-7f && nt < 14) { ++nt; r *= d / (float)nt; } }
    float ec = expf(c0 * sc);
#pragma unroll
    for (int q = 0; q < 8; ++q) {
        int idx = q * 32 + lane; int r = idx >> 4, c = idx & 15;
        float v = t1[idx];
        R[idx] = (r == c ? 1.f : 0.f) + v;
        t2[idx] = v;
    }
    __syncwarp();
    float* P = t2; float* P2 = t3;
    for (int k = 2; k <= nt; ++k) {
        wmm16(P2, P, t1, lane);
        float ik = 1.f / (float)k;
#pragma unroll
        for (int q = 0; q < 8; ++q) { int idx = q * 32 + lane; float v = P2[idx] * ik; P2[idx] = v; R[idx] += v; }
        __syncwarp();
        float* tm = P; P = P2; P2 = tm;
    }
#pragma unroll
    for (int q = 0; q < 8; ++q) R[q * 32 + lane] *= ec;
    __syncwarp();
    for (int q2 = 0; q2 < j; ++q2) {
        wmm16(t2, R, R, lane);
#pragma unroll
        for (int q = 0; q < 8; ++q) R[q * 32 + lane] = t2[q * 32 + lane];
        __syncwarp();
    }
}

// =========================================================================
// K2 (fused samplemean+prep): one 256-thread block.
//  stage1: per-sample means -> g_xmean; grand mean G accumulated inline.
//  stage2: warp0 (Gs,Gi)=sqrt/invsqrt(G) || warp1 (As,Ai) of running_mean.
// =========================================================================
__global__ __launch_bounds__(256) void k_prep2(const float* __restrict__ rm) {
    __shared__ __align__(16) float ws[2][6][256];
    int t = threadIdx.x, w = t >> 5, lane = t & 31;
    float g = 0.f;
    for (int b = 0; b < S_N; ++b) {
        float acc = 0.f;
#pragma unroll 8
        for (int c = 0; c < CHUNKS; ++c) acc += g_partial[(b * CHUNKS + c) * NE + t];
        acc *= (1.f / (float)TVM);
        g_xmean[b * NE + t] = acc;
        g += acc;
    }
    ws[0][0][t] = g * (1.f / (float)S_N);   // G -> warp0's b0
    ws[1][0][t] = rm[t];                    // running_mean -> warp1's b0
    __syncthreads();
    if (w == 0) {
        w_sqrtinv(ws[0][0], ws[0][1], ws[0][2], ws[0][3], ws[0][4], ws[0][5], lane);
#pragma unroll
        for (int q = 0; q < 8; ++q) { int idx = q * 32 + lane; g_Gs[idx] = ws[0][1][idx]; g_Gi[idx] = ws[0][2][idx]; }
    } else if (w == 1) {
        w_sqrtinv(ws[1][0], ws[1][1], ws[1][2], ws[1][3], ws[1][4], ws[1][5], lane);
#pragma unroll
        for (int q = 0; q < 8; ++q) { int idx = q * 32 + lane; g_As[idx] = ws[1][1][idx]; g_Ai[idx] = ws[1][2][idx]; }
    }
}

// =========================================================================
// K3: L_b = logm(Gi * xmean_b * Gi); 32 one-warp blocks in parallel.
// =========================================================================
__global__ __launch_bounds__(32) void k_logm() {
    __shared__ __align__(16) float m[6][256];
    int b = blockIdx.x, lane = threadIdx.x;
#pragma unroll
    for (int q = 0; q < 8; ++q) {
        int idx = q * 32 + lane;
        m[0][idx] = g_Gi[idx];
        m[1][idx] = g_xmean[b * NE + idx];
    }
    __syncwarp();
    wmm16(m[2], m[0], m[1], lane);
    wmm16(m[3], m[2], m[0], lane);
    w_logm(m[3], m[0], m[1], m[2], m[4], m[5], lane);
#pragma unroll
    for (int q = 0; q < 8; ++q) { int idx = q * 32 + lane; g_L[b * NE + idx] = m[3][idx]; }
}

// =========================================================================
// K4: mean = Gs expm(mean L) Gs; warp0: C = invsqrt(mean) -> g_C
//     || warp1: geodesic(rm, mean, 0.1) -> out tail.
// =========================================================================
__global__ __launch_bounds__(64) void k_finish(float* __restrict__ out_tail, int write_tail) {
    __shared__ __align__(16) float ws[2][6][256];
    __shared__ __align__(16) float sMean[256];
    int t = threadIdx.x, w = t >> 5, lane = t & 31;
    float* b0 = ws[w][0]; float* b1 = ws[w][1]; float* b2 = ws[w][2];
    float* b3 = ws[w][3]; float* b4 = ws[w][4]; float* b5 = ws[w][5];
    if (w == 0) {
#pragma unroll
        for (int q = 0; q < 8; ++q) {
            int idx = q * 32 + lane;
            float acc = 0.f;
#pragma unroll 8
            for (int b = 0; b < S_N; ++b) acc += g_L[b * NE + idx];
            b0[idx] = acc * (1.f / (float)S_N);
        }
        __syncwarp();
        w_expm(b0, b1, b2, b3, b4, lane);
        {
#pragma unroll
            for (int q = 0; q < 8; ++q) { int idx = q * 32 + lane; b2[idx] = g_Gs[idx]; }
            __syncwarp();
        }
        wmm16(b3, b2, b1, lane);
        wmm16(sMean, b3, b2, lane);
    }
    __syncthreads();
    if (w == 0) {
        w_sqrtinv(sMean, b0, b1, b2, b3, b4, lane);
#pragma unroll
        for (int q = 0; q < 8; ++q) { int idx = q * 32 + lane; g_C[idx] = b1[idx]; }
    } else {
#pragma unroll
        for (int q = 0; q < 8; ++q) { int idx = q * 32 + lane; b0[idx] = g_Ai[idx]; }
        __syncwarp();
        wmm16(b1, b0, sMean, lane);
        wmm16(b2, b1, b0, lane);
        w_logm(b2, b0, b1, b3, b4, b5, lane);
#pragma unroll
        for (int q = 0; q < 8; ++q) b2[q * 32 + lane] *= 0.1f;
        __syncwarp();
        w_expm(b2, b0, b1, b3, b4, lane);
#pragma unroll
        for (int q = 0; q < 8; ++q) { int idx = q * 32 + lane; b1[idx] = g_As[idx]; }
        __syncwarp();
        wmm16(b3, b1, b0, lane);
        wmm16(b4, b3, b1, lane);
        if (write_tail) {
#pragma unroll
            for (int q = 0; q < 8; ++q) { int idx = q * 32 + lane; out_tail[idx] = b4[idx]; }
        }
    }
}

// =========================================================================
// K5 (transform v6): Y = C*X*C. 1 row/thread, 16 matrices/block.
//  phase A: w_i = sum_k C[i,k] * x_k   (X rows broadcast from staged smem;
//           C[i,k] = Cs[k*16+i] by symmetry, 1 small LDS per k)
//  phase B: y_i = w_i * C              (C rows uniform broadcast)
//  Output staged through smem -> fully coalesced STG (fixes 4x store-
//  wavefront inflation of the direct per-row stores).
//  ~60 regs, no spills, registers-only between phases.
// =========================================================================
typedef unsigned long long u64;
__device__ __forceinline__ u64 pk2(float lo, float hi) {
    u64 r; asm("mov.b64 %0, {%1, %2};" : "=l"(r) : "f"(lo), "f"(hi)); return r;
}
__device__ __forceinline__ void upk2(u64 v, float& lo, float& hi) {
    asm("mov.b64 {%0, %1}, %2;" : "=f"(lo), "=f"(hi) : "l"(v));
}
__device__ __forceinline__ u64 ffma2(u64 a, u64 b, u64 c) {
    u64 d; asm("fma.rn.f32x2 %0, %1, %2, %3;" : "=l"(d) : "l"(a), "l"(b), "l"(c)); return d;
}

#define MPB   16
#define XS4   66    // per-matrix float4 stride in Xs (1056 B)
#define YST   20    // Ys row stride in floats

__global__ __launch_bounds__(256) void k_transform(const float* __restrict__ X,
                                                   float* __restrict__ Y) {
    __shared__ float4 Xs4[MPB * XS4];                    // 16.5 KB
    __shared__ float  Cs[256];
    __shared__ __align__(16) float Ysm[MPB * 16 * YST];  // 20 KB
    int t = threadIdx.x;
    Cs[t] = g_C[t];

    const float4* xg = (const float4*)(X + (size_t)blockIdx.x * (MPB * NE));
#pragma unroll
    for (int j = 0; j < 4; ++j) {
        int g = t + 256 * j;
        Xs4[(g >> 6) * XS4 + (g & 63)] = xg[g];
    }
    __syncthreads();

    int m = t >> 4, i = t & 15;
    const float4* xm = Xs4 + m * XS4;

    // phase A: w = sum_k C[i,k] * x_k
    u64 w[8];
#pragma unroll
    for (int q = 0; q < 8; ++q) w[q] = pk2(0.f, 0.f);
#pragma unroll
    for (int k = 0; k < 16; ++k) {
        float ck = Cs[k * 16 + i];          // C[i][k] by symmetry
        float4 a = xm[k * 4], b = xm[k * 4 + 1], c = xm[k * 4 + 2], d = xm[k * 4 + 3];
        u64 s = pk2(ck, ck);
        w[0] = ffma2(s, pk2(a.x, a.y), w[0]);
        w[1] = ffma2(s, pk2(a.z, a.w), w[1]);
        w[2] = ffma2(s, pk2(b.x, b.y), w[2]);
        w[3] = ffma2(s, pk2(b.z, b.w), w[3]);
        w[4] = ffma2(s, pk2(c.x, c.y), w[4]);
        w[5] = ffma2(s, pk2(c.z, c.w), w[5]);
        w[6] = ffma2(s, pk2(d.x, d.y), w[6]);
        w[7] = ffma2(s, pk2(d.z, d.w), w[7]);
    }
    float wf[16];
#pragma unroll
    for (int q = 0; q < 8; ++q) upk2(w[q], wf[2 * q], wf[2 * q + 1]);

    // phase B: y = w * C  (C rows uniform broadcast)
    u64 y[8];
#pragma unroll
    for (int q = 0; q < 8; ++q) y[q] = pk2(0.f, 0.f);
#pragma unroll
    for (int k = 0; k < 16; ++k) {
        const float4* cp = (const float4*)(Cs + k * 16);
        float4 a = cp[0], b = cp[1], c = cp[2], d = cp[3];
        u64 s = pk2(wf[k], wf[k]);
        y[0] = ffma2(s, pk2(a.x, a.y), y[0]);
        y[1] = ffma2(s, pk2(a.z, a.w), y[1]);
        y[2] = ffma2(s, pk2(b.x, b.y), y[2]);
        y[3] = ffma2(s, pk2(b.z, b.w), y[3]);
        y[4] = ffma2(s, pk2(c.x, c.y), y[4]);
        y[5] = ffma2(s, pk2(c.z, c.w), y[5]);
        y[6] = ffma2(s, pk2(d.x, d.y), y[6]);
        y[7] = ffma2(s, pk2(d.z, d.w), y[7]);
    }

    // stage Y in smem, then coalesced global store
    {
        float* yr = Ysm + (m * 16 + i) * YST;
#pragma unroll
        for (int q = 0; q < 4; ++q) {
            float4 v;
            upk2(y[2 * q], v.x, v.y);
            upk2(y[2 * q + 1], v.z, v.w);
            *(float4*)(yr + 4 * q) = v;
        }
    }
    __syncthreads();
    float4* yg = (float4*)(Y + (size_t)blockIdx.x * (MPB * NE));
#pragma unroll
    for (int j = 0; j < 4; ++j) {
        int g = t + 256 * j;
        int mm = g >> 6, f = g & 63;
        int row = f >> 2, q = f & 3;
        yg[g] = *(const float4*)(Ysm + (mm * 16 + row) * YST + 4 * q);
    }
}

// =========================================================================
extern "C" void kernel_launch(void* const* d_in, const int* in_sizes, int n_in,
                              void* d_out, int out_size) {
    const float* X = (const float*)d_in[0];
    const float* rm = (const float*)d_in[1];
    float* out = (float*)d_out;
    long long n_x = in_sizes[0];           // 26,214,400
    int nmat = (int)(n_x >> 8);            // 102,400
    int write_tail = ((long long)out_size - n_x) >= NE ? 1 : 0;

    k_partial<<<dim3(S_N, CHUNKS), 256>>>(X);
    k_prep2<<<1, 256>>>(rm);
    k_logm<<<S_N, 32>>>();
    k_finish<<<1, 64>>>(out + n_x, write_tail);
    k_transform<<<nmat / MPB, 256>>>(X, out);
}

// round 12
// speedup vs baseline: 1.4936x; 1.4572x over previous
#include <cuda_runtime.h>
#include <math.h>

// Problem shape (fixed by setup_inputs): X (32, 64, 25, 2, 16, 16) fp32.
#define S_N     32
#define TVM     3200
#define NE      256
#define CHUNKS  32
#define CHUNK_M 100

// ---------------- device scratch (no allocations allowed) ----------------
__device__ float g_partial[S_N * CHUNKS * NE];
__device__ float g_xmean[S_N * NE];
__device__ float g_L[S_N * NE];
__device__ float g_Gs[NE], g_Gi[NE];
__device__ float g_As[NE], g_Ai[NE];
__device__ float g_C[NE];

// =========================================================================
// K1: partial reduction of X. grid (32,32), 256 thr; 100 matrices / block.
// =========================================================================
__global__ __launch_bounds__(256) void k_partial(const float* __restrict__ X) {
    __shared__ float4 red[256];
    int s = blockIdx.x, c = blockIdx.y, t = threadIdx.x;
    int j = t & 63, gsub = t >> 6;
    const float4* p = (const float4*)(X + ((size_t)s * TVM + (size_t)c * CHUNK_M) * NE)
                      + (size_t)gsub * 25 * 64 + j;
    float4 a = make_float4(0.f, 0.f, 0.f, 0.f);
#pragma unroll
    for (int m = 0; m < 25; ++m) {
        float4 v = p[(size_t)m * 64];
        a.x += v.x; a.y += v.y; a.z += v.z; a.w += v.w;
    }
    red[t] = a;
    __syncthreads();
    if (t < 64) {
        float4 b0 = red[t], b1 = red[t + 64], b2 = red[t + 128], b3 = red[t + 192];
        float4 r = make_float4((b0.x + b1.x) + (b2.x + b3.x),
                               (b0.y + b1.y) + (b2.y + b3.y),
                               (b0.z + b1.z) + (b2.z + b3.z),
                               (b0.w + b1.w) + (b2.w + b3.w));
        ((float4*)(g_partial + (s * CHUNKS + c) * NE))[t] = r;
    }
}

// =========================================================================
// K2: per-sample means. grid 32, 256 thr (chip-parallel; do NOT fuse).
// =========================================================================
__global__ __launch_bounds__(256) void k_samplemean() {
    int b = blockIdx.x, t = threadIdx.x;
    float acc = 0.f;
#pragma unroll 8
    for (int c = 0; c < CHUNKS; ++c) acc += g_partial[(b * CHUNKS + c) * NE + t];
    g_xmean[b * NE + t] = acc * (1.f / (float)TVM);
}

// =========================================================================
// Warp-level 16x16 toolkit (matrix = 256 contiguous floats, row-major).
// Iteration counts derived ONCE from the initial error norm.
// =========================================================================
__device__ __forceinline__ float wsum32(float v) {
#pragma unroll
    for (int o = 16; o; o >>= 1) v += __shfl_xor_sync(0xffffffffu, v, o);
    return v;
}
__device__ __forceinline__ float wmax32(float v) {
#pragma unroll
    for (int o = 16; o; o >>= 1) v = fmaxf(v, __shfl_xor_sync(0xffffffffu, v, o));
    return v;
}
__device__ __forceinline__ float w_trace16(const float* A, int lane) {
    float v = (lane < 16) ? A[lane * 17] : 0.f;
    return wsum32(v);
}

__device__ __forceinline__ void wmm16(float* C, const float* A, const float* B, int lane) {
    int i = lane >> 1, jb = (lane & 1) << 3;
    const float4* ar = (const float4*)(A + i * 16);
    float4 v0 = ar[0], v1 = ar[1], v2 = ar[2], v3 = ar[3];
    float a[16] = {v0.x, v0.y, v0.z, v0.w, v1.x, v1.y, v1.z, v1.w,
                   v2.x, v2.y, v2.z, v2.w, v3.x, v3.y, v3.z, v3.w};
    float c[8] = {0.f, 0.f, 0.f, 0.f, 0.f, 0.f, 0.f, 0.f};
#pragma unroll
    for (int k = 0; k < 16; ++k) {
        const float4* br = (const float4*)(B + k * 16 + jb);
        float4 b0 = br[0], b1 = br[1];
        float ak = a[k];
        c[0] = fmaf(ak, b0.x, c[0]); c[1] = fmaf(ak, b0.y, c[1]);
        c[2] = fmaf(ak, b0.z, c[2]); c[3] = fmaf(ak, b0.w, c[3]);
        c[4] = fmaf(ak, b1.x, c[4]); c[5] = fmaf(ak, b1.y, c[5]);
        c[6] = fmaf(ak, b1.z, c[6]); c[7] = fmaf(ak, b1.w, c[7]);
    }
    __syncwarp();
    float4* cr = (float4*)(C + i * 16 + jb);
    cr[0] = make_float4(c[0], c[1], c[2], c[3]);
    cr[1] = make_float4(c[4], c[5], c[6], c[7]);
    __syncwarp();
}

__device__ void w_sqrtinv(const float* A, float* Y, float* Z,
                          float* T, float* Y2, float* Z2, int lane) {
    float s = w_trace16(A, lane) * (1.f / 16.f);
    float is0 = 1.f / s, d2 = 0.f;
#pragma unroll
    for (int q = 0; q < 8; ++q) {
        int idx = q * 32 + lane; int r = idx >> 4, c = idx & 15;
        float v = A[idx] * is0 - (r == c ? 1.f : 0.f);
        d2 += v * v;
    }
    d2 = wsum32(d2);
    int n;
    if (d2 >= 0.81f) {
        float rs = 0.f;
        if (lane < 16) { for (int k = 0; k < 16; ++k) rs += fabsf(A[lane * 16 + k]); }
        rs = wmax32(rs);
        s = rs; is0 = 1.f / s; n = 12;
    } else {
        float cur = sqrtf(d2); n = 0;
        while (cur > 1e-7f && n < 7) { cur = 1.3f * cur * cur; ++n; }
    }
#pragma unroll
    for (int q = 0; q < 8; ++q) {
        int idx = q * 32 + lane; int r = idx >> 4, c = idx & 15;
        Y[idx] = A[idx] * is0;
        Z[idx] = (r == c) ? 1.f : 0.f;
    }
    __syncwarp();
    float* y = Y; float* z = Z; float* y2 = Y2; float* z2 = Z2;
    for (int it = 0; it < n; ++it) {
        wmm16(T, z, y, lane);
#pragma unroll
        for (int q = 0; q < 8; ++q) {
            int idx = q * 32 + lane; int r = idx >> 4, c = idx & 15;
            T[idx] = 0.5f * ((r == c ? 3.f : 0.f) - T[idx]);
        }
        __syncwarp();
        wmm16(y2, y, T, lane);
        wmm16(z2, T, z, lane);
        float* tm = y; y = y2; y2 = tm;
        tm = z; z = z2; z2 = tm;
    }
    float fs = sqrtf(s), fi = rsqrtf(s);
    float ry[8], rz[8];
#pragma unroll
    for (int q = 0; q < 8; ++q) { int idx = q * 32 + lane; ry[q] = y[idx] * fs; rz[q] = z[idx] * fi; }
    __syncwarp();
#pragma unroll
    for (int q = 0; q < 8; ++q) { int idx = q * 32 + lane; Y[idx] = ry[q]; Z[idx] = rz[q]; }
    __syncwarp();
}

__device__ void w_logm(float* B, float* t1, float* t2, float* t3,
                       float* t4, float* t5, int lane) {
    int jsq = 0; float s, d2;
    for (;;) {
        s = w_trace16(B, lane) * (1.f / 16.f);
        float is = 1.f / s; d2 = 0.f;
#pragma unroll
        for (int q = 0; q < 8; ++q) {
            int idx = q * 32 + lane; int r = idx >> 4, c = idx & 15;
            float v = B[idx] * is - (r == c ? 1.f : 0.f);
            t1[idx] = v; d2 += v * v;
        }
        __syncwarp();
        d2 = wsum32(d2);
        if (d2 <= 0.25f || jsq >= 4) break;
        w_sqrtinv(B, t2, t3, t4, t5, t1, lane);
        float r8[8];
#pragma unroll
        for (int q = 0; q < 8; ++q) r8[q] = t2[q * 32 + lane];
        __syncwarp();
#pragma unroll
        for (int q = 0; q < 8; ++q) B[q * 32 + lane] = r8[q];
        __syncwarp();
        ++jsq;
    }
    float d = sqrtf(d2);
    int nt = 1; { float r = d; while (r > 1e-7f && nt < 24) { r *= d; ++nt; } }
    float lns = logf(s);
#pragma unroll
    for (int q = 0; q < 8; ++q) {
        int idx = q * 32 + lane; int r = idx >> 4, c = idx & 15;
        float v = t1[idx];
        B[idx] = (r == c ? lns : 0.f) + v;
        t2[idx] = v;
    }
    __syncwarp();
    float* P = t2; float* P2 = t3; float sg = 1.f;
    for (int k = 2; k <= nt; ++k) {
        wmm16(P2, P, t1, lane);
        sg = -sg; float cf = sg / (float)k;
#pragma unroll
        for (int q = 0; q < 8; ++q) { int idx = q * 32 + lane; B[idx] += cf * P2[idx]; }
        __syncwarp();
        float* tm = P; P = P2; P2 = tm;
    }
    if (jsq) {
        float f = (float)(1 << jsq);
#pragma unroll
        for (int q = 0; q < 8; ++q) B[q * 32 + lane] *= f;
        __syncwarp();
    }
}

__device__ void w_expm(const float* A, float* R, float* t1, float* t2, float* t3, int lane) {
    float c0 = w_trace16(A, lane) * (1.f / 16.f);
    float d2 = 0.f;
#pragma unroll
    for (int q = 0; q < 8; ++q) {
        int idx = q * 32 + lane; int r = idx >> 4, c = idx & 15;
        float v = A[idx] - (r == c ? c0 : 0.f);
        t1[idx] = v; d2 += v * v;
    }
    __syncwarp();
    d2 = wsum32(d2);
    int j = 0; float sc = 1.f;
    while (d2 > 0.25f && j < 20) { sc *= 0.5f; d2 *= 0.25f; ++j; }
    if (j) {
#pragma unroll
        for (int q = 0; q < 8; ++q) t1[q * 32 + lane] *= sc;
        __syncwarp();
    }
    float d = sqrtf(d2);
    int nt = 1; { float r = d; while (r > 1e-7f && nt < 14) { ++nt; r *= d / (float)nt; } }
    float ec = expf(c0 * sc);
#pragma unroll
    for (int q = 0; q < 8; ++q) {
        int idx = q * 32 + lane; int r = idx >> 4, c = idx & 15;
        float v = t1[idx];
        R[idx] = (r == c ? 1.f : 0.f) + v;
        t2[idx] = v;
    }
    __syncwarp();
    float* P = t2; float* P2 = t3;
    for (int k = 2; k <= nt; ++k) {
        wmm16(P2, P, t1, lane);
        float ik = 1.f / (float)k;
#pragma unroll
        for (int q = 0; q < 8; ++q) { int idx = q * 32 + lane; float v = P2[idx] * ik; P2[idx] = v; R[idx] += v; }
        __syncwarp();
        float* tm = P; P = P2; P2 = tm;
    }
#pragma unroll
    for (int q = 0; q < 8; ++q) R[q * 32 + lane] *= ec;
    __syncwarp();
    for (int q2 = 0; q2 < j; ++q2) {
        wmm16(t2, R, R, lane);
#pragma unroll
        for (int q = 0; q < 8; ++q) R[q * 32 + lane] = t2[q * 32 + lane];
        __syncwarp();
    }
}

// =========================================================================
// K3: prep, 256 threads. All threads do the G-sum (32 LDG each, high MLP);
// then warp0: (Gs,Gi)=sqrt/invsqrt(G) || warp1: (As,Ai) of running_mean.
// =========================================================================
__global__ __launch_bounds__(256) void k_prep(const float* __restrict__ rm) {
    __shared__ __align__(16) float ws[2][6][256];
    int t = threadIdx.x, w = t >> 5, lane = t & 31;
    {
        float acc = 0.f;
#pragma unroll 8
        for (int b = 0; b < S_N; ++b) acc += g_xmean[b * NE + t];
        ws[0][0][t] = acc * (1.f / (float)S_N);
        ws[1][0][t] = rm[t];
    }
    __syncthreads();
    if (w == 0) {
        w_sqrtinv(ws[0][0], ws[0][1], ws[0][2], ws[0][3], ws[0][4], ws[0][5], lane);
#pragma unroll
        for (int q = 0; q < 8; ++q) { int idx = q * 32 + lane; g_Gs[idx] = ws[0][1][idx]; g_Gi[idx] = ws[0][2][idx]; }
    } else if (w == 1) {
        w_sqrtinv(ws[1][0], ws[1][1], ws[1][2], ws[1][3], ws[1][4], ws[1][5], lane);
#pragma unroll
        for (int q = 0; q < 8; ++q) { int idx = q * 32 + lane; g_As[idx] = ws[1][1][idx]; g_Ai[idx] = ws[1][2][idx]; }
    }
}

// =========================================================================
// K4: L_b = logm(Gi * xmean_b * Gi); 32 one-warp blocks in parallel.
// =========================================================================
__global__ __launch_bounds__(32) void k_logm() {
    __shared__ __align__(16) float m[6][256];
    int b = blockIdx.x, lane = threadIdx.x;
#pragma unroll
    for (int q = 0; q < 8; ++q) {
        int idx = q * 32 + lane;
        m[0][idx] = g_Gi[idx];
        m[1][idx] = g_xmean[b * NE + idx];
    }
    __syncwarp();
    wmm16(m[2], m[0], m[1], lane);
    wmm16(m[3], m[2], m[0], lane);
    w_logm(m[3], m[0], m[1], m[2], m[4], m[5], lane);
#pragma unroll
    for (int q = 0; q < 8; ++q) { int idx = q * 32 + lane; g_L[b * NE + idx] = m[3][idx]; }
}

// =========================================================================
// K5: finish, 256 threads. All threads do the L-sum (32 LDG each); then
// warp0: mean = Gs expm(Lbar) Gs; sync; warp0: C=invsqrt(mean) -> g_C
// || warp1: geodesic(rm, mean, 0.1) -> out tail.
// =========================================================================
__global__ __launch_bounds__(256) void k_finish(float* __restrict__ out_tail, int write_tail) {
    __shared__ __align__(16) float ws[2][6][256];
    __shared__ __align__(16) float sMean[256];
    __shared__ __align__(16) float sLbar[256];
    int t = threadIdx.x, w = t >> 5, lane = t & 31;
    float* b0 = ws[w & 1][0]; float* b1 = ws[w & 1][1]; float* b2 = ws[w & 1][2];
    float* b3 = ws[w & 1][3]; float* b4 = ws[w & 1][4]; float* b5 = ws[w & 1][5];
    {
        float acc = 0.f;
#pragma unroll 8
        for (int b = 0; b < S_N; ++b) acc += g_L[b * NE + t];
        sLbar[t] = acc * (1.f / (float)S_N);
    }
    __syncthreads();
    if (w == 0) {
        w_expm(sLbar, b1, b2, b3, b4, lane);      // b1 = expm(Lbar)
#pragma unroll
        for (int q = 0; q < 8; ++q) { int idx = q * 32 + lane; b2[idx] = g_Gs[idx]; }
        __syncwarp();
        wmm16(b3, b2, b1, lane);
        wmm16(sMean, b3, b2, lane);               // Karcher mean
    }
    __syncthreads();
    if (w == 0) {
        w_sqrtinv(sMean, b0, b1, b2, b3, b4, lane);
#pragma unroll
        for (int q = 0; q < 8; ++q) { int idx = q * 32 + lane; g_C[idx] = b1[idx]; }
    } else if (w == 1) {
#pragma unroll
        for (int q = 0; q < 8; ++q) { int idx = q * 32 + lane; b0[idx] = g_Ai[idx]; }
        __syncwarp();
        wmm16(b1, b0, sMean, lane);
        wmm16(b2, b1, b0, lane);                  // M = Ai mean Ai
        w_logm(b2, b0, b1, b3, b4, b5, lane);
#pragma unroll
        for (int q = 0; q < 8; ++q) b2[q * 32 + lane] *= 0.1f;
        __syncwarp();
        w_expm(b2, b0, b1, b3, b4, lane);         // b0 = M^0.1
#pragma unroll
        for (int q = 0; q < 8; ++q) { int idx = q * 32 + lane; b1[idx] = g_As[idx]; }
        __syncwarp();
        wmm16(b3, b1, b0, lane);
        wmm16(b4, b3, b1, lane);                  // new running mean
        if (write_tail) {
#pragma unroll
            for (int q = 0; q < 8; ++q) { int idx = q * 32 + lane; out_tail[idx] = b4[idx]; }
        }
    }
}

// =========================================================================
// K6 (transform v6): Y = C*X*C. 1 row/thread, 16 matrices/block.
//  phase A: w_i = sum_k C[i,k] * x_k  (X rows from staged smem; C[i,k] =
//           Cs[k*16+i] by symmetry); phase B: y_i = w_i * C (broadcast).
//  Output staged through smem -> fully coalesced STG.
// =========================================================================
typedef unsigned long long u64;
__device__ __forceinline__ u64 pk2(float lo, float hi) {
    u64 r; asm("mov.b64 %0, {%1, %2};" : "=l"(r) : "f"(lo), "f"(hi)); return r;
}
__device__ __forceinline__ void upk2(u64 v, float& lo, float& hi) {
    asm("mov.b64 {%0, %1}, %2;" : "=f"(lo), "=f"(hi) : "l"(v));
}
__device__ __forceinline__ u64 ffma2(u64 a, u64 b, u64 c) {
    u64 d; asm("fma.rn.f32x2 %0, %1, %2, %3;" : "=l"(d) : "l"(a), "l"(b), "l"(c)); return d;
}

#define MPB   16
#define XS4   66    // per-matrix float4 stride in Xs (1056 B)
#define YST   20    // Ys row stride in floats

__global__ __launch_bounds__(256) void k_transform(const float* __restrict__ X,
                                                   float* __restrict__ Y) {
    __shared__ float4 Xs4[MPB * XS4];
    __shared__ float  Cs[256];
    __shared__ __align__(16) float Ysm[MPB * 16 * YST];
    int t = threadIdx.x;
    Cs[t] = g_C[t];

    const float4* xg = (const float4*)(X + (size_t)blockIdx.x * (MPB * NE));
#pragma unroll
    for (int j = 0; j < 4; ++j) {
        int g = t + 256 * j;
        Xs4[(g >> 6) * XS4 + (g & 63)] = xg[g];
    }
    __syncthreads();

    int m = t >> 4, i = t & 15;
    const float4* xm = Xs4 + m * XS4;

    // phase A: w = sum_k C[i,k] * x_k
    u64 w[8];
#pragma unroll
    for (int q = 0; q < 8; ++q) w[q] = pk2(0.f, 0.f);
#pragma unroll
    for (int k = 0; k < 16; ++k) {
        float ck = Cs[k * 16 + i];
        float4 a = xm[k * 4], b = xm[k * 4 + 1], c = xm[k * 4 + 2], d = xm[k * 4 + 3];
        u64 s = pk2(ck, ck);
        w[0] = ffma2(s, pk2(a.x, a.y), w[0]);
        w[1] = ffma2(s, pk2(a.z, a.w), w[1]);
        w[2] = ffma2(s, pk2(b.x, b.y), w[2]);
        w[3] = ffma2(s, pk2(b.z, b.w), w[3]);
        w[4] = ffma2(s, pk2(c.x, c.y), w[4]);
        w[5] = ffma2(s, pk2(c.z, c.w), w[5]);
        w[6] = ffma2(s, pk2(d.x, d.y), w[6]);
        w[7] = ffma2(s, pk2(d.z, d.w), w[7]);
    }
    float wf[16];
#pragma unroll
    for (int q = 0; q < 8; ++q) upk2(w[q], wf[2 * q], wf[2 * q + 1]);

    // phase B: y = w * C
    u64 y[8];
#pragma unroll
    for (int q = 0; q < 8; ++q) y[q] = pk2(0.f, 0.f);
#pragma unroll
    for (int k = 0; k < 16; ++k) {
        const float4* cp = (const float4*)(Cs + k * 16);
        float4 a = cp[0], b = cp[1], c = cp[2], d = cp[3];
        u64 s = pk2(wf[k], wf[k]);
        y[0] = ffma2(s, pk2(a.x, a.y), y[0]);
        y[1] = ffma2(s, pk2(a.z, a.w), y[1]);
        y[2] = ffma2(s, pk2(b.x, b.y), y[2]);
        y[3] = ffma2(s, pk2(b.z, b.w), y[3]);
        y[4] = ffma2(s, pk2(c.x, c.y), y[4]);
        y[5] = ffma2(s, pk2(c.z, c.w), y[5]);
        y[6] = ffma2(s, pk2(d.x, d.y), y[6]);
        y[7] = ffma2(s, pk2(d.z, d.w), y[7]);
    }

    {
        float* yr = Ysm + (m * 16 + i) * YST;
#pragma unroll
        for (int q = 0; q < 4; ++q) {
            float4 v;
            upk2(y[2 * q], v.x, v.y);
            upk2(y[2 * q + 1], v.z, v.w);
            *(float4*)(yr + 4 * q) = v;
        }
    }
    __syncthreads();
    float4* yg = (float4*)(Y + (size_t)blockIdx.x * (MPB * NE));
#pragma unroll
    for (int j = 0; j < 4; ++j) {
        int g = t + 256 * j;
        int mm = g >> 6, f = g & 63;
        int row = f >> 2, q = f & 3;
        yg[g] = *(const float4*)(Ysm + (mm * 16 + row) * YST + 4 * q);
    }
}

// =========================================================================
extern "C" void kernel_launch(void* const* d_in, const int* in_sizes, int n_in,
                              void* d_out, int out_size) {
    const float* X = (const float*)d_in[0];
    const float* rm = (const float*)d_in[1];
    float* out = (float*)d_out;
    long long n_x = in_sizes[0];           // 26,214,400
    int nmat = (int)(n_x >> 8);            // 102,400
    int write_tail = ((long long)out_size - n_x) >= NE ? 1 : 0;

    k_partial<<<dim3(S_N, CHUNKS), 256>>>(X);
    k_samplemean<<<S_N, 256>>>();
    k_prep<<<1, 256>>>(rm);
    k_logm<<<S_N, 32>>>();
    k_finish<<<1, 256>>>(out + n_x, write_tail);
    k_transform<<<nmat / MPB, 256>>>(X, out);
}

// round 13
// speedup vs baseline: 1.5156x; 1.0147x over previous
#include <cuda_runtime.h>
#include <math.h>

// Problem shape (fixed by setup_inputs): X (32, 64, 25, 2, 16, 16) fp32.
#define S_N     32
#define TVM     3200
#define NE      256
#define CHUNKS  32
#define CHUNK_M 100

// ---------------- device scratch (no allocations allowed) ----------------
__device__ float g_partial[S_N * CHUNKS * NE];
__device__ float g_xmean[S_N * NE];
__device__ float g_L[S_N * NE];
__device__ float g_Gs[NE], g_Gi[NE];
__device__ float g_As[NE], g_Ai[NE];
__device__ float g_C[NE];

// =========================================================================
// K1: partial reduction of X. grid (32,32), 256 thr; 100 matrices / block.
// =========================================================================
__global__ __launch_bounds__(256) void k_partial(const float* __restrict__ X) {
    __shared__ float4 red[256];
    int s = blockIdx.x, c = blockIdx.y, t = threadIdx.x;
    int j = t & 63, gsub = t >> 6;
    const float4* p = (const float4*)(X + ((size_t)s * TVM + (size_t)c * CHUNK_M) * NE)
                      + (size_t)gsub * 25 * 64 + j;
    float4 a = make_float4(0.f, 0.f, 0.f, 0.f);
#pragma unroll
    for (int m = 0; m < 25; ++m) {
        float4 v = p[(size_t)m * 64];
        a.x += v.x; a.y += v.y; a.z += v.z; a.w += v.w;
    }
    red[t] = a;
    __syncthreads();
    if (t < 64) {
        float4 b0 = red[t], b1 = red[t + 64], b2 = red[t + 128], b3 = red[t + 192];
        float4 r = make_float4((b0.x + b1.x) + (b2.x + b3.x),
                               (b0.y + b1.y) + (b2.y + b3.y),
                               (b0.z + b1.z) + (b2.z + b3.z),
                               (b0.w + b1.w) + (b2.w + b3.w));
        ((float4*)(g_partial + (s * CHUNKS + c) * NE))[t] = r;
    }
}

// =========================================================================
// K2: per-sample means. grid 32, 256 thr (chip-parallel; do NOT fuse).
// =========================================================================
__global__ __launch_bounds__(256) void k_samplemean() {
    int b = blockIdx.x, t = threadIdx.x;
    float acc = 0.f;
#pragma unroll 8
    for (int c = 0; c < CHUNKS; ++c) acc += g_partial[(b * CHUNKS + c) * NE + t];
    g_xmean[b * NE + t] = acc * (1.f / (float)TVM);
}

// =========================================================================
// Warp-level 16x16 toolkit (matrix = 256 contiguous floats, row-major).
// Iteration counts derived ONCE from the initial error norm.
// Convergence targets 3e-6 (output gate is 1e-3; measured slack ~300x).
// =========================================================================
__device__ __forceinline__ float wsum32(float v) {
#pragma unroll
    for (int o = 16; o; o >>= 1) v += __shfl_xor_sync(0xffffffffu, v, o);
    return v;
}
__device__ __forceinline__ float wmax32(float v) {
#pragma unroll
    for (int o = 16; o; o >>= 1) v = fmaxf(v, __shfl_xor_sync(0xffffffffu, v, o));
    return v;
}
__device__ __forceinline__ float w_trace16(const float* A, int lane) {
    float v = (lane < 16) ? A[lane * 17] : 0.f;
    return wsum32(v);
}

__device__ __forceinline__ void wmm16(float* C, const float* A, const float* B, int lane) {
    int i = lane >> 1, jb = (lane & 1) << 3;
    const float4* ar = (const float4*)(A + i * 16);
    float4 v0 = ar[0], v1 = ar[1], v2 = ar[2], v3 = ar[3];
    float a[16] = {v0.x, v0.y, v0.z, v0.w, v1.x, v1.y, v1.z, v1.w,
                   v2.x, v2.y, v2.z, v2.w, v3.x, v3.y, v3.z, v3.w};
    float c[8] = {0.f, 0.f, 0.f, 0.f, 0.f, 0.f, 0.f, 0.f};
#pragma unroll
    for (int k = 0; k < 16; ++k) {
        const float4* br = (const float4*)(B + k * 16 + jb);
        float4 b0 = br[0], b1 = br[1];
        float ak = a[k];
        c[0] = fmaf(ak, b0.x, c[0]); c[1] = fmaf(ak, b0.y, c[1]);
        c[2] = fmaf(ak, b0.z, c[2]); c[3] = fmaf(ak, b0.w, c[3]);
        c[4] = fmaf(ak, b1.x, c[4]); c[5] = fmaf(ak, b1.y, c[5]);
        c[6] = fmaf(ak, b1.z, c[6]); c[7] = fmaf(ak, b1.w, c[7]);
    }
    __syncwarp();
    float4* cr = (float4*)(C + i * 16 + jb);
    cr[0] = make_float4(c[0], c[1], c[2], c[3]);
    cr[1] = make_float4(c[4], c[5], c[6], c[7]);
    __syncwarp();
}

__device__ void w_sqrtinv(const float* A, float* Y, float* Z,
                          float* T, float* Y2, float* Z2, int lane) {
    float s = w_trace16(A, lane) * (1.f / 16.f);
    float is0 = 1.f / s, d2 = 0.f;
#pragma unroll
    for (int q = 0; q < 8; ++q) {
        int idx = q * 32 + lane; int r = idx >> 4, c = idx & 15;
        float v = A[idx] * is0 - (r == c ? 1.f : 0.f);
        d2 += v * v;
    }
    d2 = wsum32(d2);
    int n;
    if (d2 >= 0.81f) {
        float rs = 0.f;
        if (lane < 16) { for (int k = 0; k < 16; ++k) rs += fabsf(A[lane * 16 + k]); }
        rs = wmax32(rs);
        s = rs; is0 = 1.f / s; n = 12;
    } else {
        float cur = sqrtf(d2); n = 0;
        while (cur > 3e-6f && n < 7) { cur = 1.3f * cur * cur; ++n; }
    }
#pragma unroll
    for (int q = 0; q < 8; ++q) {
        int idx = q * 32 + lane; int r = idx >> 4, c = idx & 15;
        Y[idx] = A[idx] * is0;
        Z[idx] = (r == c) ? 1.f : 0.f;
    }
    __syncwarp();
    float* y = Y; float* z = Z; float* y2 = Y2; float* z2 = Z2;
    for (int it = 0; it < n; ++it) {
        wmm16(T, z, y, lane);
#pragma unroll
        for (int q = 0; q < 8; ++q) {
            int idx = q * 32 + lane; int r = idx >> 4, c = idx & 15;
            T[idx] = 0.5f * ((r == c ? 3.f : 0.f) - T[idx]);
        }
        __syncwarp();
        wmm16(y2, y, T, lane);
        wmm16(z2, T, z, lane);
        float* tm = y; y = y2; y2 = tm;
        tm = z; z = z2; z2 = tm;
    }
    float fs = sqrtf(s), fi = rsqrtf(s);
    float ry[8], rz[8];
#pragma unroll
    for (int q = 0; q < 8; ++q) { int idx = q * 32 + lane; ry[q] = y[idx] * fs; rz[q] = z[idx] * fi; }
    __syncwarp();
#pragma unroll
    for (int q = 0; q < 8; ++q) { int idx = q * 32 + lane; Y[idx] = ry[q]; Z[idx] = rz[q]; }
    __syncwarp();
}

__device__ void w_logm(float* B, float* t1, float* t2, float* t3,
                       float* t4, float* t5, int lane) {
    int jsq = 0; float s, d2;
    for (;;) {
        s = w_trace16(B, lane) * (1.f / 16.f);
        float is = 1.f / s; d2 = 0.f;
#pragma unroll
        for (int q = 0; q < 8; ++q) {
            int idx = q * 32 + lane; int r = idx >> 4, c = idx & 15;
            float v = B[idx] * is - (r == c ? 1.f : 0.f);
            t1[idx] = v; d2 += v * v;
        }
        __syncwarp();
        d2 = wsum32(d2);
        if (d2 <= 0.25f || jsq >= 4) break;
        w_sqrtinv(B, t2, t3, t4, t5, t1, lane);
        float r8[8];
#pragma unroll
        for (int q = 0; q < 8; ++q) r8[q] = t2[q * 32 + lane];
        __syncwarp();
#pragma unroll
        for (int q = 0; q < 8; ++q) B[q * 32 + lane] = r8[q];
        __syncwarp();
        ++jsq;
    }
    float d = sqrtf(d2);
    int nt = 1; { float r = d; while (r > 3e-6f && nt < 24) { r *= d; ++nt; } }
    float lns = logf(s);
#pragma unroll
    for (int q = 0; q < 8; ++q) {
        int idx = q * 32 + lane; int r = idx >> 4, c = idx & 15;
        float v = t1[idx];
        B[idx] = (r == c ? lns : 0.f) + v;
        t2[idx] = v;
    }
    __syncwarp();
    float* P = t2; float* P2 = t3; float sg = 1.f;
    for (int k = 2; k <= nt; ++k) {
        wmm16(P2, P, t1, lane);
        sg = -sg; float cf = sg / (float)k;
#pragma unroll
        for (int q = 0; q < 8; ++q) { int idx = q * 32 + lane; B[idx] += cf * P2[idx]; }
        __syncwarp();
        float* tm = P; P = P2; P2 = tm;
    }
    if (jsq) {
        float f = (float)(1 << jsq);
#pragma unroll
        for (int q = 0; q < 8; ++q) B[q * 32 + lane] *= f;
        __syncwarp();
    }
}

__device__ void w_expm(const float* A, float* R, float* t1, float* t2, float* t3, int lane) {
    float c0 = w_trace16(A, lane) * (1.f / 16.f);
    float d2 = 0.f;
#pragma unroll
    for (int q = 0; q < 8; ++q) {
        int idx = q * 32 + lane; int r = idx >> 4, c = idx & 15;
        float v = A[idx] - (r == c ? c0 : 0.f);
        t1[idx] = v; d2 += v * v;
    }
    __syncwarp();
    d2 = wsum32(d2);
    int j = 0; float sc = 1.f;
    while (d2 > 0.25f && j < 20) { sc *= 0.5f; d2 *= 0.25f; ++j; }
    if (j) {
#pragma unroll
        for (int q = 0; q < 8; ++q) t1[q * 32 + lane] *= sc;
        __syncwarp();
    }
    float d = sqrtf(d2);
    int nt = 1; { float r = d; while (r > 3e-6f && nt < 14) { ++nt; r *= d / (float)nt; } }
    float ec = expf(c0 * sc);
#pragma unroll
    for (int q = 0; q < 8; ++q) {
        int idx = q * 32 + lane; int r = idx >> 4, c = idx & 15;
        float v = t1[idx];
        R[idx] = (r == c ? 1.f : 0.f) + v;
        t2[idx] = v;
    }
    __syncwarp();
    float* P = t2; float* P2 = t3;
    for (int k = 2; k <= nt; ++k) {
        wmm16(P2, P, t1, lane);
        float ik = 1.f / (float)k;
#pragma unroll
        for (int q = 0; q < 8; ++q) { int idx = q * 32 + lane; float v = P2[idx] * ik; P2[idx] = v; R[idx] += v; }
        __syncwarp();
        float* tm = P; P = P2; P2 = tm;
    }
#pragma unroll
    for (int q = 0; q < 8; ++q) R[q * 32 + lane] *= ec;
    __syncwarp();
    for (int q2 = 0; q2 < j; ++q2) {
        wmm16(t2, R, R, lane);
#pragma unroll
        for (int q = 0; q < 8; ++q) R[q * 32 + lane] = t2[q * 32 + lane];
        __syncwarp();
    }
}

// =========================================================================
// K3: prep, 256 threads. All threads do the G-sum (32 LDG each, high MLP);
// then warp0: (Gs,Gi)=sqrt/invsqrt(G) || warp1: (As,Ai) of running_mean.
// =========================================================================
__global__ __launch_bounds__(256) void k_prep(const float* __restrict__ rm) {
    __shared__ __align__(16) float ws[2][6][256];
    int t = threadIdx.x, w = t >> 5, lane = t & 31;
    {
        float acc = 0.f;
#pragma unroll 8
        for (int b = 0; b < S_N; ++b) acc += g_xmean[b * NE + t];
        ws[0][0][t] = acc * (1.f / (float)S_N);
        ws[1][0][t] = rm[t];
    }
    __syncthreads();
    if (w == 0) {
        w_sqrtinv(ws[0][0], ws[0][1], ws[0][2], ws[0][3], ws[0][4], ws[0][5], lane);
#pragma unroll
        for (int q = 0; q < 8; ++q) { int idx = q * 32 + lane; g_Gs[idx] = ws[0][1][idx]; g_Gi[idx] = ws[0][2][idx]; }
    } else if (w == 1) {
        w_sqrtinv(ws[1][0], ws[1][1], ws[1][2], ws[1][3], ws[1][4], ws[1][5], lane);
#pragma unroll
        for (int q = 0; q < 8; ++q) { int idx = q * 32 + lane; g_As[idx] = ws[1][1][idx]; g_Ai[idx] = ws[1][2][idx]; }
    }
}

// =========================================================================
// K4: L_b = logm(Gi * xmean_b * Gi); 32 one-warp blocks in parallel.
// =========================================================================
__global__ __launch_bounds__(32) void k_logm() {
    __shared__ __align__(16) float m[6][256];
    int b = blockIdx.x, lane = threadIdx.x;
#pragma unroll
    for (int q = 0; q < 8; ++q) {
        int idx = q * 32 + lane;
        m[0][idx] = g_Gi[idx];
        m[1][idx] = g_xmean[b * NE + idx];
    }
    __syncwarp();
    wmm16(m[2], m[0], m[1], lane);
    wmm16(m[3], m[2], m[0], lane);
    w_logm(m[3], m[0], m[1], m[2], m[4], m[5], lane);
#pragma unroll
    for (int q = 0; q < 8; ++q) { int idx = q * 32 + lane; g_L[b * NE + idx] = m[3][idx]; }
}

// =========================================================================
// K5: finish, 256 threads. All threads do the L-sum (32 LDG each); then
// warp0: mean = Gs expm(Lbar) Gs; sync; warp0: C=invsqrt(mean) -> g_C
// || warp1: geodesic(rm, mean, 0.1) -> out tail.
// =========================================================================
__global__ __launch_bounds__(256) void k_finish(float* __restrict__ out_tail, int write_tail) {
    __shared__ __align__(16) float ws[2][6][256];
    __shared__ __align__(16) float sMean[256];
    __shared__ __align__(16) float sLbar[256];
    int t = threadIdx.x, w = t >> 5, lane = t & 31;
    float* b0 = ws[w & 1][0]; float* b1 = ws[w & 1][1]; float* b2 = ws[w & 1][2];
    float* b3 = ws[w & 1][3]; float* b4 = ws[w & 1][4]; float* b5 = ws[w & 1][5];
    {
        float acc = 0.f;
#pragma unroll 8
        for (int b = 0; b < S_N; ++b) acc += g_L[b * NE + t];
        sLbar[t] = acc * (1.f / (float)S_N);
    }
    __syncthreads();
    if (w == 0) {
        w_expm(sLbar, b1, b2, b3, b4, lane);      // b1 = expm(Lbar)
#pragma unroll
        for (int q = 0; q < 8; ++q) { int idx = q * 32 + lane; b2[idx] = g_Gs[idx]; }
        __syncwarp();
        wmm16(b3, b2, b1, lane);
        wmm16(sMean, b3, b2, lane);               // Karcher mean
    }
    __syncthreads();
    if (w == 0) {
        w_sqrtinv(sMean, b0, b1, b2, b3, b4, lane);
#pragma unroll
        for (int q = 0; q < 8; ++q) { int idx = q * 32 + lane; g_C[idx] = b1[idx]; }
    } else if (w == 1) {
#pragma unroll
        for (int q = 0; q < 8; ++q) { int idx = q * 32 + lane; b0[idx] = g_Ai[idx]; }
        __syncwarp();
        wmm16(b1, b0, sMean, lane);
        wmm16(b2, b1, b0, lane);                  // M = Ai mean Ai
        w_logm(b2, b0, b1, b3, b4, b5, lane);
#pragma unroll
        for (int q = 0; q < 8; ++q) b2[q * 32 + lane] *= 0.1f;
        __syncwarp();
        w_expm(b2, b0, b1, b3, b4, lane);         // b0 = M^0.1
#pragma unroll
        for (int q = 0; q < 8; ++q) { int idx = q * 32 + lane; b1[idx] = g_As[idx]; }
        __syncwarp();
        wmm16(b3, b1, b0, lane);
        wmm16(b4, b3, b1, lane);                  // new running mean
        if (write_tail) {
#pragma unroll
            for (int q = 0; q < 8; ++q) { int idx = q * 32 + lane; out_tail[idx] = b4[idx]; }
        }
    }
}

// =========================================================================
// K6 (transform v7): Y = C*X*C. 1 row/thread, 16 matrices/block.
// v6 + smem aliasing: after phase A the X tile is dead, so the Y staging
// reuses the same buffer (guarded by __syncthreads) -> smem/block drops
// 38.5 -> ~22.5 KB, roughly doubling resident blocks per SM.
// =========================================================================
typedef unsigned long long u64;
__device__ __forceinline__ u64 pk2(float lo, float hi) {
    u64 r; asm("mov.b64 %0, {%1, %2};" : "=l"(r) : "f"(lo), "f"(hi)); return r;
}
__device__ __forceinline__ void upk2(u64 v, float& lo, float& hi) {
    asm("mov.b64 {%0, %1}, %2;" : "=f"(lo), "=f"(hi) : "l"(v));
}
__device__ __forceinline__ u64 ffma2(u64 a, u64 b, u64 c) {
    u64 d; asm("fma.rn.f32x2 %0, %1, %2, %3;" : "=l"(d) : "l"(a), "l"(b), "l"(c)); return d;
}

#define MPB   16
#define XS4   66     // per-matrix float4 stride in X view (1056 B)
#define YST   20     // Y view row stride (floats)
#define YMS   (16*YST)  // Y view matrix stride = 320 floats
#define SBUF  (MPB * YMS)  // 5120 floats = 20.5 KB (>= MPB*XS4*4 floats)

__global__ __launch_bounds__(256) void k_transform(const float* __restrict__ X,
                                                   float* __restrict__ Y) {
    __shared__ float4 Buf4[SBUF / 4];     // aliased: X tile then Y staging
    __shared__ float  Cs[256];
    float* Buf = (float*)Buf4;
    int t = threadIdx.x;
    Cs[t] = g_C[t];

    const float4* xg = (const float4*)(X + (size_t)blockIdx.x * (MPB * NE));
#pragma unroll
    for (int j = 0; j < 4; ++j) {
        int g = t + 256 * j;
        Buf4[(g >> 6) * XS4 + (g & 63)] = xg[g];
    }
    __syncthreads();

    int m = t >> 4, i = t & 15;
    const float4* xm = Buf4 + m * XS4;

    // phase A: w = sum_k C[i,k] * x_k   (C[i,k] = Cs[k*16+i] by symmetry)
    u64 w[8];
#pragma unroll
    for (int q = 0; q < 8; ++q) w[q] = pk2(0.f, 0.f);
#pragma unroll
    for (int k = 0; k < 16; ++k) {
        float ck = Cs[k * 16 + i];
        float4 a = xm[k * 4], b = xm[k * 4 + 1], c = xm[k * 4 + 2], d = xm[k * 4 + 3];
        u64 s = pk2(ck, ck);
        w[0] = ffma2(s, pk2(a.x, a.y), w[0]);
        w[1] = ffma2(s, pk2(a.z, a.w), w[1]);
        w[2] = ffma2(s, pk2(b.x, b.y), w[2]);
        w[3] = ffma2(s, pk2(b.z, b.w), w[3]);
        w[4] = ffma2(s, pk2(c.x, c.y), w[4]);
        w[5] = ffma2(s, pk2(c.z, c.w), w[5]);
        w[6] = ffma2(s, pk2(d.x, d.y), w[6]);
        w[7] = ffma2(s, pk2(d.z, d.w), w[7]);
    }
    float wf[16];
#pragma unroll
    for (int q = 0; q < 8; ++q) upk2(w[q], wf[2 * q], wf[2 * q + 1]);

    // phase B: y = w * C   (C rows uniform broadcast)
    u64 y[8];
#pragma unroll
    for (int q = 0; q < 8; ++q) y[q] = pk2(0.f, 0.f);
#pragma unroll
    for (int k = 0; k < 16; ++k) {
        const float4* cp = (const float4*)(Cs + k * 16);
        float4 a = cp[0], b = cp[1], c = cp[2], d = cp[3];
        u64 s = pk2(wf[k], wf[k]);
        y[0] = ffma2(s, pk2(a.x, a.y), y[0]);
        y[1] = ffma2(s, pk2(a.z, a.w), y[1]);
        y[2] = ffma2(s, pk2(b.x, b.y), y[2]);
        y[3] = ffma2(s, pk2(b.z, b.w), y[3]);
        y[4] = ffma2(s, pk2(c.x, c.y), y[4]);
        y[5] = ffma2(s, pk2(c.z, c.w), y[5]);
        y[6] = ffma2(s, pk2(d.x, d.y), y[6]);
        y[7] = ffma2(s, pk2(d.z, d.w), y[7]);
    }

    // X tile fully consumed -> safe to overwrite buffer with Y staging
    __syncthreads();
    {
        float* yr = Buf + m * YMS + i * YST;
#pragma unroll
        for (int q = 0; q < 4; ++q) {
            float4 v;
            upk2(y[2 * q], v.x, v.y);
            upk2(y[2 * q + 1], v.z, v.w);
            *(float4*)(yr + 4 * q) = v;
        }
    }
    __syncthreads();
    float4* yg = (float4*)(Y + (size_t)blockIdx.x * (MPB * NE));
#pragma unroll
    for (int j = 0; j < 4; ++j) {
        int g = t + 256 * j;
        int mm = g >> 6, f = g & 63;
        int row = f >> 2, q = f & 3;
        yg[g] = *(const float4*)(Buf + mm * YMS + row * YST + 4 * q);
    }
}

// =========================================================================
extern "C" void kernel_launch(void* const* d_in, const int* in_sizes, int n_in,
                              void* d_out, int out_size) {
    const float* X = (const float*)d_in[0];
    const float* rm = (const float*)d_in[1];
    float* out = (float*)d_out;
    long long n_x = in_sizes[0];           // 26,214,400
    int nmat = (int)(n_x >> 8);            // 102,400
    int write_tail = ((long long)out_size - n_x) >= NE ? 1 : 0;

    k_partial<<<dim3(S_N, CHUNKS), 256>>>(X);
    k_samplemean<<<S_N, 256>>>();
    k_prep<<<1, 256>>>(rm);
    k_logm<<<S_N, 32>>>();
    k_finish<<<1, 256>>>(out + n_x, write_tail);
    k_transform<<<nmat / MPB, 256>>>(X, out);
}